// round 1
// baseline (speedup 1.0000x reference)
#include <cuda_runtime.h>
#include <math.h>

#define Bn 32
#define Ln 1024
#define Hn 12
#define DV 64
#define MN 128          // M = 2*Mh
#define HDIM 768
#define BH (Bn*Hn)      // 384
#define TOK (Bn*Ln)     // 32768

// ---------------- device scratch (static, no allocation) ----------------
__device__ float g_q   [BH*Ln*DV];        // (b,h,l,d)
__device__ float g_v   [BH*Ln*DV];
__device__ float g_phi [BH*Ln*MN];        // (b,h,l,m)  ~201MB
__device__ float g_tQ  [BH*Ln*MN];        // (b,h,l,m)
__device__ float g_om  [Hn*DV*64];        // scaled omega (h,d,m)
__device__ float g_amp [Hn];
__device__ float g_G   [BH*MN*MN];
__device__ float g_C   [BH*MN*DV];
__device__ float g_Linv[BH*MN*MN];
__device__ float g_S   [BH*MN*DV];
__device__ float g_sf  [TOK*HDIM];        // sample features (b,l,hdim)
__device__ float g_klbh[BH];

// ---------------- helpers ----------------
__device__ __forceinline__ float blk_sum(float v, float* red) {
    int tid = threadIdx.x;
#pragma unroll
    for (int o = 16; o; o >>= 1) v += __shfl_xor_sync(0xffffffffu, v, o);
    __syncthreads();
    if ((tid & 31) == 0) red[tid >> 5] = v;
    __syncthreads();
    if (tid < 32) {
        float r = (tid < 8) ? red[tid] : 0.0f;
#pragma unroll
        for (int o = 4; o; o >>= 1) r += __shfl_xor_sync(0xffffffffu, r, o);
        if (tid == 0) red[0] = r;
    }
    __syncthreads();
    return red[0];
}

// ---------------- K0: prep scaled omega + amp ----------------
__global__ void k0_prep(const float* __restrict__ log_sf,
                        const float* __restrict__ log_ls,
                        const float* __restrict__ omega_half) {
    int idx = blockIdx.x * blockDim.x + threadIdx.x;
    const int NOM = Hn * DV * 64;
    if (idx < NOM) {
        int h = idx / (DV * 64);
        int d = (idx / 64) % DV;
        float scale = 1.41421356237309515f * expf(-log_ls[h * DV + d]);
        g_om[idx] = omega_half[idx] * scale;
    }
    if (idx < Hn) g_amp[idx] = sqrtf(expf(log_sf[idx]));
}

// ---------------- K1: qv = x @ W_qv^T ; split into q,v (b,h,l,d) ----------------
__global__ void __launch_bounds__(256) k1_qv(const float* __restrict__ x,
                                             const float* __restrict__ Wqv) {
    __shared__ float As[16][64];
    __shared__ float Bs[16][64];
    int bx = blockIdx.x;       // j tile: 24
    int by = blockIdx.y;       // n tile: 512
    int tid = threadIdx.x;
    int tx = tid & 15, ty = tid >> 4;
    float acc[4][4] = {};
    int arow  = tid >> 2;          // 0..63
    int acol4 = (tid & 3) * 4;     // 0,4,8,12
    const float* xA = x   + (size_t)(by * 64 + arow) * HDIM;
    const float* wB = Wqv + (size_t)(bx * 64 + arow) * HDIM;
    for (int k0 = 0; k0 < HDIM; k0 += 16) {
        float4 av = *(const float4*)(xA + k0 + acol4);
        float4 bv = *(const float4*)(wB + k0 + acol4);
        As[acol4 + 0][arow] = av.x; As[acol4 + 1][arow] = av.y;
        As[acol4 + 2][arow] = av.z; As[acol4 + 3][arow] = av.w;
        Bs[acol4 + 0][arow] = bv.x; Bs[acol4 + 1][arow] = bv.y;
        Bs[acol4 + 2][arow] = bv.z; Bs[acol4 + 3][arow] = bv.w;
        __syncthreads();
#pragma unroll
        for (int kk = 0; kk < 16; kk++) {
            float4 a = *(const float4*)&As[kk][ty * 4];
            float4 b = *(const float4*)&Bs[kk][tx * 4];
            acc[0][0] += a.x * b.x; acc[0][1] += a.x * b.y; acc[0][2] += a.x * b.z; acc[0][3] += a.x * b.w;
            acc[1][0] += a.y * b.x; acc[1][1] += a.y * b.y; acc[1][2] += a.y * b.z; acc[1][3] += a.y * b.w;
            acc[2][0] += a.z * b.x; acc[2][1] += a.z * b.y; acc[2][2] += a.z * b.z; acc[2][3] += a.z * b.w;
            acc[3][0] += a.w * b.x; acc[3][1] += a.w * b.y; acc[3][2] += a.w * b.z; acc[3][3] += a.w * b.w;
        }
        __syncthreads();
    }
#pragma unroll
    for (int i = 0; i < 4; i++) {
        int row = by * 64 + ty * 4 + i;
        int b = row >> 10, l = row & 1023;
#pragma unroll
        for (int j = 0; j < 4; j++) {
            int col = bx * 64 + tx * 4 + j;
            int h = col >> 7, r = col & 127;
            if (r < 64) g_q[((size_t)(b * Hn + h) * Ln + l) * DV + r]        = acc[i][j];
            else        g_v[((size_t)(b * Hn + h) * Ln + l) * DV + (r - 64)] = acc[i][j];
        }
    }
}

// ---------------- K2: proj = q @ omega + phase ; phi = amp/sqrt(M)*[cos,sin] ----------------
__global__ void __launch_bounds__(256) k2_phi(const float* __restrict__ phase) {
    __shared__ float qs[64][64];   // [d][l]
    __shared__ float oms[64][64];  // [d][m]
    int l0 = blockIdx.x * 64;
    int bh = blockIdx.y;
    int h  = bh % Hn;
    int tid = threadIdx.x;
    int tx = tid & 15, ty = tid >> 4;
    int r = tid >> 2;                // 0..63
    int cbase = (tid & 3) * 16;      // 0,16,32,48
    const float* qrow = g_q + ((size_t)bh * Ln + l0 + r) * DV;
    const float* orow = g_om + (size_t)h * DV * 64 + r * 64;
#pragma unroll
    for (int c = 0; c < 4; c++) {
        float4 qv4 = *(const float4*)(qrow + cbase + c * 4);
        qs[cbase + c * 4 + 0][r] = qv4.x; qs[cbase + c * 4 + 1][r] = qv4.y;
        qs[cbase + c * 4 + 2][r] = qv4.z; qs[cbase + c * 4 + 3][r] = qv4.w;
        *(float4*)&oms[r][cbase + c * 4] = *(const float4*)(orow + cbase + c * 4);
    }
    __syncthreads();
    float acc[4][4] = {};
#pragma unroll
    for (int kk = 0; kk < 64; kk++) {
        float4 a = *(const float4*)&qs[kk][ty * 4];
        float4 b = *(const float4*)&oms[kk][tx * 4];
        acc[0][0] += a.x * b.x; acc[0][1] += a.x * b.y; acc[0][2] += a.x * b.z; acc[0][3] += a.x * b.w;
        acc[1][0] += a.y * b.x; acc[1][1] += a.y * b.y; acc[1][2] += a.y * b.z; acc[1][3] += a.y * b.w;
        acc[2][0] += a.z * b.x; acc[2][1] += a.z * b.y; acc[2][2] += a.z * b.z; acc[2][3] += a.z * b.w;
        acc[3][0] += a.w * b.x; acc[3][1] += a.w * b.y; acc[3][2] += a.w * b.z; acc[3][3] += a.w * b.w;
    }
    float sc = g_amp[h] * 0.08838834764831845f;   // amp / sqrt(128)
#pragma unroll
    for (int i = 0; i < 4; i++) {
        int l = l0 + ty * 4 + i;
        float* pb = g_phi + ((size_t)bh * Ln + l) * MN;
#pragma unroll
        for (int j = 0; j < 4; j++) {
            int m = tx * 4 + j;
            float p = acc[i][j] + phase[h * 64 + m];
            float s, c;
            sincosf(p, &s, &c);
            pb[m]      = sc * c;
            pb[m + 64] = sc * s;
        }
    }
}

// ---------------- K3: G = phi^T phi, C = phi^T v (per bh) ----------------
__global__ void __launch_bounds__(256) k3_gram() {
    __shared__ float As[16][128];
    __shared__ float Bs[16][64];
    int nb = blockIdx.x;   // 0,1 -> G cols, 2 -> C
    int bh = blockIdx.y;
    int tid = threadIdx.x;
    int tx = tid & 15, ty = tid >> 4;
    float acc[8][4] = {};
    int ra = tid >> 4;            // 0..15
    int ca = (tid & 15) * 8;      // A cols
    int cb = (tid & 15) * 4;      // B cols
    for (int l0 = 0; l0 < Ln; l0 += 16) {
        const float* prow = g_phi + ((size_t)bh * Ln + l0 + ra) * MN;
        *(float4*)&As[ra][ca]     = *(const float4*)(prow + ca);
        *(float4*)&As[ra][ca + 4] = *(const float4*)(prow + ca + 4);
        if (nb < 2)
            *(float4*)&Bs[ra][cb] = *(const float4*)(prow + nb * 64 + cb);
        else
            *(float4*)&Bs[ra][cb] = *(const float4*)(g_v + ((size_t)bh * Ln + l0 + ra) * DV + cb);
        __syncthreads();
#pragma unroll
        for (int kk = 0; kk < 16; kk++) {
            float4 a0 = *(const float4*)&As[kk][ty * 8];
            float4 a1 = *(const float4*)&As[kk][ty * 8 + 4];
            float4 b  = *(const float4*)&Bs[kk][tx * 4];
            float av[8] = {a0.x, a0.y, a0.z, a0.w, a1.x, a1.y, a1.z, a1.w};
            float bv[4] = {b.x, b.y, b.z, b.w};
#pragma unroll
            for (int i = 0; i < 8; i++)
#pragma unroll
                for (int j = 0; j < 4; j++) acc[i][j] += av[i] * bv[j];
        }
        __syncthreads();
    }
#pragma unroll
    for (int i = 0; i < 8; i++) {
        int m = ty * 8 + i;
#pragma unroll
        for (int j = 0; j < 4; j++) {
            int n = tx * 4 + j;
            if (nb < 2) g_G[(size_t)bh * MN * MN + m * MN + nb * 64 + n] = acc[i][j];
            else        g_C[(size_t)bh * MN * DV + m * DV + n]           = acc[i][j];
        }
    }
}

// ---------------- K4: Cholesky, L^{-1}, S = Linv C, KL terms (per bh) ----------------
__global__ void __launch_bounds__(256) k4_factor(const float* __restrict__ log_sigma2) {
    extern __shared__ float sm[];
    float* sA  = sm;            // 128x128
    float* sLi = sm + 16384;    // 128x128
    float* sC  = sm + 32768;    // 128x64
    float* sS  = sm + 40960;    // 128x64
    __shared__ float red[8];
    __shared__ float sval;
    int bh = blockIdx.x;
    int tid = threadIdx.x;
    float sigma2 = expf(log_sigma2[0]);

    for (int i = tid; i < 16384; i += 256) sA[i] = g_G[(size_t)bh * 16384 + i];
    __syncthreads();
    if (tid < 128) sA[tid * 129] += sigma2 + 1e-6f;
    __syncthreads();

    // Cholesky (right-looking), lower triangle in sA
    for (int j = 0; j < 128; j++) {
        if (tid == 0) {
            float d = sqrtf(sA[j * 128 + j]);
            sA[j * 128 + j] = d;
            sval = 1.0f / d;
        }
        __syncthreads();
        float invd = sval;
        if (tid > j && tid < 128) sA[tid * 128 + j] *= invd;
        __syncthreads();
        if (tid > j && tid < 128) {
            float lij = sA[tid * 128 + j];
            for (int k = j + 1; k <= tid; k++) sA[tid * 128 + k] -= lij * sA[k * 128 + j];
        }
        __syncthreads();
    }

    float ld = (tid < 128) ? logf(sA[tid * 129]) : 0.0f;
    float logdetA = 2.0f * blk_sum(ld, red);

    // Linv (forward substitution, one column per thread)
    for (int i = tid; i < 16384; i += 256) sLi[i] = 0.0f;
    __syncthreads();
    if (tid < 128) {
        int j = tid;
        sLi[j * 128 + j] = 1.0f / sA[j * 128 + j];
        for (int i = j + 1; i < 128; i++) {
            float s = 0.0f;
            for (int k = j; k < i; k++) s += sA[i * 128 + k] * sLi[k * 128 + j];
            sLi[i * 128 + j] = -s / sA[i * 128 + i];
        }
    }
    __syncthreads();

    float tr = 0.0f;
    for (int i = tid; i < 16384; i += 256) tr += sLi[i] * sLi[i];
    float tr_Ainv = blk_sum(tr, red);

    for (int i = tid; i < 16384; i += 256) g_Linv[(size_t)bh * 16384 + i] = sLi[i];
    for (int i = tid; i < 8192; i += 256) sC[i] = g_C[(size_t)bh * 8192 + i];
    __syncthreads();

    // S = Linv @ C  (Linv lower triangular)
    for (int idx = tid; idx < 8192; idx += 256) {
        int m = idx >> 6, d = idx & 63;
        float s = 0.0f;
        for (int k = 0; k <= m; k++) s += sLi[m * 128 + k] * sC[k * 64 + d];
        sS[idx] = s;
    }
    __syncthreads();
    for (int i = tid; i < 8192; i += 256) g_S[(size_t)bh * 8192 + i] = sS[i];

    // mu_norm2 = || Linv^T @ S ||^2
    float mu = 0.0f;
    for (int idx = tid; idx < 8192; idx += 256) {
        int m = idx >> 6, d = idx & 63;
        float s = 0.0f;
        for (int k = m; k < 128; k++) s += sLi[k * 128 + m] * sS[k * 64 + d];
        mu += s * s;
    }
    float mu_norm2 = blk_sum(mu, red);

    if (tid == 0) {
        float kl = 0.5f * (64.0f * sigma2 * tr_Ainv + mu_norm2 - 8192.0f
                           - 64.0f * (128.0f * logf(sigma2) - logdetA));
        g_klbh[bh] = kl;
    }
}

// ---------------- K5: tQ = phi @ Linv^T ----------------
__global__ void __launch_bounds__(256) k5_tq() {
    __shared__ float As[16][64];
    __shared__ float Bs[16][64];
    int m0 = blockIdx.x * 64;
    int l0 = blockIdx.y * 64;
    int bh = blockIdx.z;
    int tid = threadIdx.x;
    int tx = tid & 15, ty = tid >> 4;
    float acc[4][4] = {};
    int r = tid >> 2;              // 0..63
    int c4 = (tid & 3) * 4;
    for (int k0 = 0; k0 < 128; k0 += 16) {
        float4 a = *(const float4*)(g_phi + ((size_t)bh * Ln + l0 + r) * MN + k0 + c4);
        float4 b = *(const float4*)(g_Linv + (size_t)bh * 16384 + (m0 + r) * 128 + k0 + c4);
        As[c4 + 0][r] = a.x; As[c4 + 1][r] = a.y; As[c4 + 2][r] = a.z; As[c4 + 3][r] = a.w;
        Bs[c4 + 0][r] = b.x; Bs[c4 + 1][r] = b.y; Bs[c4 + 2][r] = b.z; Bs[c4 + 3][r] = b.w;
        __syncthreads();
#pragma unroll
        for (int kk = 0; kk < 16; kk++) {
            float4 a4 = *(const float4*)&As[kk][ty * 4];
            float4 b4 = *(const float4*)&Bs[kk][tx * 4];
            acc[0][0] += a4.x * b4.x; acc[0][1] += a4.x * b4.y; acc[0][2] += a4.x * b4.z; acc[0][3] += a4.x * b4.w;
            acc[1][0] += a4.y * b4.x; acc[1][1] += a4.y * b4.y; acc[1][2] += a4.y * b4.z; acc[1][3] += a4.y * b4.w;
            acc[2][0] += a4.z * b4.x; acc[2][1] += a4.z * b4.y; acc[2][2] += a4.z * b4.z; acc[2][3] += a4.z * b4.w;
            acc[3][0] += a4.w * b4.x; acc[3][1] += a4.w * b4.y; acc[3][2] += a4.w * b4.z; acc[3][3] += a4.w * b4.w;
        }
        __syncthreads();
    }
#pragma unroll
    for (int i = 0; i < 4; i++) {
        float* dst = g_tQ + ((size_t)bh * Ln + l0 + ty * 4 + i) * MN + m0;
#pragma unroll
        for (int j = 0; j < 4; j++) dst[tx * 4 + j] = acc[i][j];
    }
}

// ---------------- K6: mean = tQ@S, var = sigma2*rowsum(tQ^2), features ----------------
__global__ void __launch_bounds__(256) k6_meanvar(const float* __restrict__ log_sigma2,
                                                  const float* __restrict__ eps) {
    __shared__ float As[16][64];
    __shared__ float Bs[16][64];
    __shared__ float var_s[64];
    int l0 = blockIdx.x * 64;
    int bh = blockIdx.y;
    int b = bh / Hn, h = bh % Hn;
    int tid = threadIdx.x;
    int tx = tid & 15, ty = tid >> 4;
    float acc[4][4] = {};
    float sq = 0.0f;
    int r = tid >> 2;
    int c4 = (tid & 3) * 4;
    int rb = tid >> 4, cb = (tid & 15) * 4;
    for (int k0 = 0; k0 < 128; k0 += 16) {
        float4 a = *(const float4*)(g_tQ + ((size_t)bh * Ln + l0 + r) * MN + k0 + c4);
        sq += a.x * a.x + a.y * a.y + a.z * a.z + a.w * a.w;
        As[c4 + 0][r] = a.x; As[c4 + 1][r] = a.y; As[c4 + 2][r] = a.z; As[c4 + 3][r] = a.w;
        *(float4*)&Bs[rb][cb] = *(const float4*)(g_S + (size_t)bh * 8192 + (k0 + rb) * 64 + cb);
        __syncthreads();
#pragma unroll
        for (int kk = 0; kk < 16; kk++) {
            float4 a4 = *(const float4*)&As[kk][ty * 4];
            float4 b4 = *(const float4*)&Bs[kk][tx * 4];
            acc[0][0] += a4.x * b4.x; acc[0][1] += a4.x * b4.y; acc[0][2] += a4.x * b4.z; acc[0][3] += a4.x * b4.w;
            acc[1][0] += a4.y * b4.x; acc[1][1] += a4.y * b4.y; acc[1][2] += a4.y * b4.z; acc[1][3] += a4.y * b4.w;
            acc[2][0] += a4.z * b4.x; acc[2][1] += a4.z * b4.y; acc[2][2] += a4.z * b4.z; acc[2][3] += a4.z * b4.w;
            acc[3][0] += a4.w * b4.x; acc[3][1] += a4.w * b4.y; acc[3][2] += a4.w * b4.z; acc[3][3] += a4.w * b4.w;
        }
        __syncthreads();
    }
    sq += __shfl_xor_sync(0xffffffffu, sq, 1);
    sq += __shfl_xor_sync(0xffffffffu, sq, 2);
    if ((tid & 3) == 0) var_s[r] = sq;
    __syncthreads();
    float sigma2 = expf(log_sigma2[0]);
#pragma unroll
    for (int i = 0; i < 4; i++) {
        int l = l0 + ty * 4 + i;
        float stdv = sqrtf(fmaxf(sigma2 * var_s[ty * 4 + i], 0.0f));
        const float* erow = eps + ((size_t)bh * Ln + l) * DV;
        float* orow = g_sf + ((size_t)(b * Ln + l)) * HDIM + h * 64;
#pragma unroll
        for (int j = 0; j < 4; j++) {
            int d = tx * 4 + j;
            orow[d] = acc[i][j] + stdv * erow[d];
        }
    }
}

// ---------------- K7: out = sf @ W_O_w^T + b ----------------
__global__ void __launch_bounds__(256) k7_out(const float* __restrict__ Wo,
                                              const float* __restrict__ bo,
                                              float* __restrict__ out) {
    __shared__ float As[16][64];
    __shared__ float Bs[16][64];
    int bx = blockIdx.x;   // o tile: 12
    int by = blockIdx.y;   // n tile: 512
    int tid = threadIdx.x;
    int tx = tid & 15, ty = tid >> 4;
    float acc[4][4] = {};
    int arow  = tid >> 2;
    int acol4 = (tid & 3) * 4;
    const float* xA = g_sf + (size_t)(by * 64 + arow) * HDIM;
    const float* wB = Wo   + (size_t)(bx * 64 + arow) * HDIM;
    for (int k0 = 0; k0 < HDIM; k0 += 16) {
        float4 av = *(const float4*)(xA + k0 + acol4);
        float4 bv = *(const float4*)(wB + k0 + acol4);
        As[acol4 + 0][arow] = av.x; As[acol4 + 1][arow] = av.y;
        As[acol4 + 2][arow] = av.z; As[acol4 + 3][arow] = av.w;
        Bs[acol4 + 0][arow] = bv.x; Bs[acol4 + 1][arow] = bv.y;
        Bs[acol4 + 2][arow] = bv.z; Bs[acol4 + 3][arow] = bv.w;
        __syncthreads();
#pragma unroll
        for (int kk = 0; kk < 16; kk++) {
            float4 a = *(const float4*)&As[kk][ty * 4];
            float4 b = *(const float4*)&Bs[kk][tx * 4];
            acc[0][0] += a.x * b.x; acc[0][1] += a.x * b.y; acc[0][2] += a.x * b.z; acc[0][3] += a.x * b.w;
            acc[1][0] += a.y * b.x; acc[1][1] += a.y * b.y; acc[1][2] += a.y * b.z; acc[1][3] += a.y * b.w;
            acc[2][0] += a.z * b.x; acc[2][1] += a.z * b.y; acc[2][2] += a.z * b.z; acc[2][3] += a.z * b.w;
            acc[3][0] += a.w * b.x; acc[3][1] += a.w * b.y; acc[3][2] += a.w * b.z; acc[3][3] += a.w * b.w;
        }
        __syncthreads();
    }
#pragma unroll
    for (int i = 0; i < 4; i++) {
        int row = by * 64 + ty * 4 + i;
#pragma unroll
        for (int j = 0; j < 4; j++) {
            int col = bx * 64 + tx * 4 + j;
            out[(size_t)row * HDIM + col] = acc[i][j] + bo[col];
        }
    }
}

// ---------------- K8: deterministic KL reduce ----------------
__global__ void k8_kl(float* __restrict__ out, int pos) {
    __shared__ float red[8];
    float s = 0.0f;
    for (int i = threadIdx.x; i < BH; i += 256) s += g_klbh[i];
    s = blk_sum(s, red);
    if (threadIdx.x == 0) out[pos] = s * (1.0f / (float)Bn);
}

// ---------------- launcher ----------------
extern "C" void kernel_launch(void* const* d_in, const int* in_sizes, int n_in,
                              void* d_out, int out_size) {
    const float* x          = (const float*)d_in[0];
    const float* W_qv       = (const float*)d_in[1];
    const float* log_sf     = (const float*)d_in[2];
    const float* log_ls     = (const float*)d_in[3];
    const float* log_sigma2 = (const float*)d_in[4];
    const float* omega_half = (const float*)d_in[5];
    const float* phase      = (const float*)d_in[6];
    const float* W_O_w      = (const float*)d_in[7];
    const float* W_O_b      = (const float*)d_in[8];
    const float* eps        = (const float*)d_in[9];
    float* out = (float*)d_out;

    cudaFuncSetAttribute(k4_factor, cudaFuncAttributeMaxDynamicSharedMemorySize, 196608);

    k0_prep<<<208, 256>>>(log_sf, log_ls, omega_half);
    k1_qv<<<dim3(24, 512), 256>>>(x, W_qv);
    k2_phi<<<dim3(16, BH), 256>>>(phase);
    k3_gram<<<dim3(3, BH), 256>>>();
    k4_factor<<<BH, 256, 196608>>>(log_sigma2);
    k5_tq<<<dim3(2, 16, BH), 256>>>();
    k6_meanvar<<<dim3(16, BH), 256>>>(log_sigma2, eps);
    k7_out<<<dim3(12, 512), 256>>>(W_O_w, W_O_b, out);
    k8_kl<<<1, 256>>>(out, out_size - 1);
}

// round 3
// speedup vs baseline: 1.0196x; 1.0196x over previous
#include <cuda_runtime.h>
#include <math.h>

#define Bn 32
#define Ln 1024
#define Hn 12
#define DV 64
#define MN 128
#define HDIM 768
#define BH (Bn*Hn)
#define TOK (Bn*Ln)

// ---------------- device scratch ----------------
__device__ float g_q  [BH*Ln*DV];
__device__ float g_v  [BH*Ln*DV];
__device__ float g_phi[BH*Ln*MN];
__device__ float g_om [Hn*DV*64];
__device__ float g_amp[Hn];
__device__ float g_G  [BH*MN*MN];
__device__ float g_C  [BH*MN*DV];
__device__ float g_P  [BH*MN*MN];      // A^{-1} = Linv^T Linv
__device__ float g_W  [BH*MN*DV];      // A^{-1} C  (== W_star)
__device__ float g_sf [TOK*HDIM];
__device__ float g_klbh[BH];

__device__ __forceinline__ float blk_sum(float v, float* red) {
    int tid = threadIdx.x;
#pragma unroll
    for (int o = 16; o; o >>= 1) v += __shfl_xor_sync(0xffffffffu, v, o);
    __syncthreads();
    if ((tid & 31) == 0) red[tid >> 5] = v;
    __syncthreads();
    if (tid < 32) {
        float r = (tid < 8) ? red[tid] : 0.0f;
#pragma unroll
        for (int o = 4; o; o >>= 1) r += __shfl_xor_sync(0xffffffffu, r, o);
        if (tid == 0) red[0] = r;
    }
    __syncthreads();
    return red[0];
}

// ---------------- K0 ----------------
__global__ void k0_prep(const float* __restrict__ log_sf,
                        const float* __restrict__ log_ls,
                        const float* __restrict__ omega_half) {
    int idx = blockIdx.x * blockDim.x + threadIdx.x;
    const int NOM = Hn * DV * 64;
    if (idx < NOM) {
        int h = idx / (DV * 64);
        int d = (idx / 64) % DV;
        float scale = 1.41421356237309515f * expf(-log_ls[h * DV + d]);
        g_om[idx] = omega_half[idx] * scale;
    }
    if (idx < Hn) g_amp[idx] = sqrtf(expf(log_sf[idx]));
}

// ---------------- gemm768: out = A[rows,768] @ Wm[cols,768]^T ----------------
// mode 0: scatter into g_q/g_v (k1).  mode 1: A := g_sf, out + bias (k7).
__global__ void __launch_bounds__(256) gemm768(const float* __restrict__ Ain,
                                               const float* __restrict__ Wm,
                                               int mode,
                                               const float* __restrict__ bias,
                                               float* __restrict__ out) {
    __shared__ float As[2][16][128];
    __shared__ float Bs[2][16][128];
    const float* A = (mode == 0) ? Ain : (const float*)g_sf;
    int cx = blockIdx.x, ry = blockIdx.y;
    int tid = threadIdx.x;
    int tx = tid & 15, ty = tid >> 4;
    int lrow = tid >> 1, lk = (tid & 1) * 8;
    const float* ap = A  + (size_t)(ry * 128 + lrow) * HDIM + lk;
    const float* bp = Wm + (size_t)(cx * 128 + lrow) * HDIM + lk;
    float acc[8][8] = {};

    float4 ra0 = *(const float4*)ap,       ra1 = *(const float4*)(ap + 4);
    float4 rb0 = *(const float4*)bp,       rb1 = *(const float4*)(bp + 4);
    As[0][lk+0][lrow]=ra0.x; As[0][lk+1][lrow]=ra0.y; As[0][lk+2][lrow]=ra0.z; As[0][lk+3][lrow]=ra0.w;
    As[0][lk+4][lrow]=ra1.x; As[0][lk+5][lrow]=ra1.y; As[0][lk+6][lrow]=ra1.z; As[0][lk+7][lrow]=ra1.w;
    Bs[0][lk+0][lrow]=rb0.x; Bs[0][lk+1][lrow]=rb0.y; Bs[0][lk+2][lrow]=rb0.z; Bs[0][lk+3][lrow]=rb0.w;
    Bs[0][lk+4][lrow]=rb1.x; Bs[0][lk+5][lrow]=rb1.y; Bs[0][lk+6][lrow]=rb1.z; Bs[0][lk+7][lrow]=rb1.w;
    __syncthreads();

    for (int s = 0; s < 48; s++) {
        int cur = s & 1;
        if (s + 1 < 48) {
            const float* a2 = ap + (s + 1) * 16;
            const float* b2 = bp + (s + 1) * 16;
            ra0 = *(const float4*)a2; ra1 = *(const float4*)(a2 + 4);
            rb0 = *(const float4*)b2; rb1 = *(const float4*)(b2 + 4);
        }
#pragma unroll
        for (int kk = 0; kk < 16; kk++) {
            float4 a0 = *(const float4*)&As[cur][kk][ty * 8];
            float4 a1 = *(const float4*)&As[cur][kk][ty * 8 + 4];
            float4 b0 = *(const float4*)&Bs[cur][kk][tx * 8];
            float4 b1 = *(const float4*)&Bs[cur][kk][tx * 8 + 4];
            float av[8] = {a0.x,a0.y,a0.z,a0.w,a1.x,a1.y,a1.z,a1.w};
            float bv[8] = {b0.x,b0.y,b0.z,b0.w,b1.x,b1.y,b1.z,b1.w};
#pragma unroll
            for (int i = 0; i < 8; i++)
#pragma unroll
                for (int j = 0; j < 8; j++) acc[i][j] += av[i] * bv[j];
        }
        if (s + 1 < 48) {
            int nx = cur ^ 1;
            As[nx][lk+0][lrow]=ra0.x; As[nx][lk+1][lrow]=ra0.y; As[nx][lk+2][lrow]=ra0.z; As[nx][lk+3][lrow]=ra0.w;
            As[nx][lk+4][lrow]=ra1.x; As[nx][lk+5][lrow]=ra1.y; As[nx][lk+6][lrow]=ra1.z; As[nx][lk+7][lrow]=ra1.w;
            Bs[nx][lk+0][lrow]=rb0.x; Bs[nx][lk+1][lrow]=rb0.y; Bs[nx][lk+2][lrow]=rb0.z; Bs[nx][lk+3][lrow]=rb0.w;
            Bs[nx][lk+4][lrow]=rb1.x; Bs[nx][lk+5][lrow]=rb1.y; Bs[nx][lk+6][lrow]=rb1.z; Bs[nx][lk+7][lrow]=rb1.w;
        }
        __syncthreads();
    }

    if (mode == 0) {
#pragma unroll
        for (int i = 0; i < 8; i++) {
            int row = ry * 128 + ty * 8 + i;
            int b = row >> 10, l = row & 1023;
            size_t base = ((size_t)(b * Hn + cx) * Ln + l) * DV;
#pragma unroll
            for (int j = 0; j < 8; j++) {
                int r = tx * 8 + j;
                if (r < 64) g_q[base + r]      = acc[i][j];
                else        g_v[base + r - 64] = acc[i][j];
            }
        }
    } else {
#pragma unroll
        for (int i = 0; i < 8; i++) {
            size_t row = (size_t)(ry * 128 + ty * 8 + i);
#pragma unroll
            for (int j = 0; j < 8; j++) {
                int col = cx * 128 + tx * 8 + j;
                out[row * HDIM + col] = acc[i][j] + bias[col];
            }
        }
    }
}

// ---------------- K2: phi ----------------
__global__ void __launch_bounds__(256) k2_phi(const float* __restrict__ phase) {
    __shared__ float qs[64][64];
    __shared__ float oms[64][64];
    int l0 = blockIdx.x * 64;
    int bh = blockIdx.y;
    int h  = bh % Hn;
    int tid = threadIdx.x;
    int tx = tid & 15, ty = tid >> 4;
    int r = tid >> 2;
    int cbase = (tid & 3) * 16;
    const float* qrow = g_q + ((size_t)bh * Ln + l0 + r) * DV;
    const float* orow = g_om + (size_t)h * DV * 64 + r * 64;
#pragma unroll
    for (int c = 0; c < 4; c++) {
        float4 qv4 = *(const float4*)(qrow + cbase + c * 4);
        qs[cbase + c*4 + 0][r] = qv4.x; qs[cbase + c*4 + 1][r] = qv4.y;
        qs[cbase + c*4 + 2][r] = qv4.z; qs[cbase + c*4 + 3][r] = qv4.w;
        *(float4*)&oms[r][cbase + c * 4] = *(const float4*)(orow + cbase + c * 4);
    }
    __syncthreads();
    float acc[4][4] = {};
#pragma unroll
    for (int kk = 0; kk < 64; kk++) {
        float4 a = *(const float4*)&qs[kk][ty * 4];
        float4 b = *(const float4*)&oms[kk][tx * 4];
        acc[0][0] += a.x*b.x; acc[0][1] += a.x*b.y; acc[0][2] += a.x*b.z; acc[0][3] += a.x*b.w;
        acc[1][0] += a.y*b.x; acc[1][1] += a.y*b.y; acc[1][2] += a.y*b.z; acc[1][3] += a.y*b.w;
        acc[2][0] += a.z*b.x; acc[2][1] += a.z*b.y; acc[2][2] += a.z*b.z; acc[2][3] += a.z*b.w;
        acc[3][0] += a.w*b.x; acc[3][1] += a.w*b.y; acc[3][2] += a.w*b.z; acc[3][3] += a.w*b.w;
    }
    float sc = g_amp[h] * 0.08838834764831845f;
#pragma unroll
    for (int i = 0; i < 4; i++) {
        int l = l0 + ty * 4 + i;
        float* pb = g_phi + ((size_t)bh * Ln + l) * MN;
#pragma unroll
        for (int j = 0; j < 4; j++) {
            int m = tx * 4 + j;
            float p = acc[i][j] + phase[h * 64 + m];
            float s, c;
            sincosf(p, &s, &c);
            pb[m]      = sc * c;
            pb[m + 64] = sc * s;
        }
    }
}

// ---------------- K3: nb0: G = phi^T phi (8x8), nb1: C = phi^T v (8x4) ----------------
__global__ void __launch_bounds__(256) k3_gram() {
    __shared__ float Ps[2][16][128];
    __shared__ float Vs[2][16][64];
    int nb = blockIdx.x, bh = blockIdx.y;
    int tid = threadIdx.x;
    int tx = tid & 15, ty = tid >> 4;
    int l1 = tid >> 5, m4 = (tid & 31) * 4;
    int vl = tid >> 4, vd4 = (tid & 15) * 4;
    const float* phib = g_phi + (size_t)bh * Ln * MN;
    const float* vb   = g_v   + (size_t)bh * Ln * DV;
    float acc[8][8] = {};

    float4 p0 = *(const float4*)(phib + (size_t)l1 * MN + m4);
    float4 p1 = *(const float4*)(phib + (size_t)(l1 + 8) * MN + m4);
    float4 vv = make_float4(0.f, 0.f, 0.f, 0.f);
    if (nb) vv = *(const float4*)(vb + (size_t)vl * DV + vd4);
    *(float4*)&Ps[0][l1][m4]     = p0;
    *(float4*)&Ps[0][l1 + 8][m4] = p1;
    if (nb) *(float4*)&Vs[0][vl][vd4] = vv;
    __syncthreads();

    for (int s = 0; s < 64; s++) {
        int cur = s & 1;
        if (s + 1 < 64) {
            int ln = (s + 1) * 16;
            p0 = *(const float4*)(phib + (size_t)(ln + l1) * MN + m4);
            p1 = *(const float4*)(phib + (size_t)(ln + l1 + 8) * MN + m4);
            if (nb) vv = *(const float4*)(vb + (size_t)(ln + vl) * DV + vd4);
        }
        if (nb == 0) {
#pragma unroll
            for (int kk = 0; kk < 16; kk++) {
                float4 a0 = *(const float4*)&Ps[cur][kk][ty * 8];
                float4 a1 = *(const float4*)&Ps[cur][kk][ty * 8 + 4];
                float4 b0 = *(const float4*)&Ps[cur][kk][tx * 8];
                float4 b1 = *(const float4*)&Ps[cur][kk][tx * 8 + 4];
                float av[8] = {a0.x,a0.y,a0.z,a0.w,a1.x,a1.y,a1.z,a1.w};
                float bv[8] = {b0.x,b0.y,b0.z,b0.w,b1.x,b1.y,b1.z,b1.w};
#pragma unroll
                for (int i = 0; i < 8; i++)
#pragma unroll
                    for (int j = 0; j < 8; j++) acc[i][j] += av[i] * bv[j];
            }
        } else {
#pragma unroll
            for (int kk = 0; kk < 16; kk++) {
                float4 a0 = *(const float4*)&Ps[cur][kk][ty * 8];
                float4 a1 = *(const float4*)&Ps[cur][kk][ty * 8 + 4];
                float4 b0 = *(const float4*)&Vs[cur][kk][tx * 4];
                float av[8] = {a0.x,a0.y,a0.z,a0.w,a1.x,a1.y,a1.z,a1.w};
                float bv[4] = {b0.x,b0.y,b0.z,b0.w};
#pragma unroll
                for (int i = 0; i < 8; i++)
#pragma unroll
                    for (int j = 0; j < 4; j++) acc[i][j] += av[i] * bv[j];
            }
        }
        if (s + 1 < 64) {
            int nx = cur ^ 1;
            *(float4*)&Ps[nx][l1][m4]     = p0;
            *(float4*)&Ps[nx][l1 + 8][m4] = p1;
            if (nb) *(float4*)&Vs[nx][vl][vd4] = vv;
        }
        __syncthreads();
    }

    if (nb == 0) {
#pragma unroll
        for (int i = 0; i < 8; i++)
#pragma unroll
            for (int j = 0; j < 8; j++)
                g_G[(size_t)bh * MN * MN + (ty * 8 + i) * MN + tx * 8 + j] = acc[i][j];
    } else {
#pragma unroll
        for (int i = 0; i < 8; i++)
#pragma unroll
            for (int j = 0; j < 4; j++)
                g_C[(size_t)bh * MN * DV + (ty * 8 + i) * DV + tx * 4 + j] = acc[i][j];
    }
}

// ---------------- K4 ----------------
__global__ void __launch_bounds__(256) k4_factor(const float* __restrict__ log_sigma2) {
    extern __shared__ float sm[];
    float* sA  = sm;            // 128x128
    float* sLi = sm + 16384;    // 128x128
    float* sC  = sm + 32768;    // 128x64
    float* sS  = sm + 40960;    // 128x64
    __shared__ float red[8];
    __shared__ float sval;
    int bh = blockIdx.x;
    int tid = threadIdx.x;
    float sigma2 = expf(log_sigma2[0]);

    for (int i = tid; i < 16384; i += 256) sA[i] = g_G[(size_t)bh * 16384 + i];
    for (int i = tid; i < 8192;  i += 256) sC[i] = g_C[(size_t)bh * 8192 + i];
    __syncthreads();
    if (tid < 128) sA[tid * 129] += sigma2 + 1e-6f;
    __syncthreads();

    for (int j = 0; j < 128; j++) {
        if (tid == 0) {
            float d = sqrtf(sA[j * 128 + j]);
            sA[j * 128 + j] = d;
            sval = 1.0f / d;
        }
        __syncthreads();
        float invd = sval;
        if (tid > j && tid < 128) sA[tid * 128 + j] *= invd;
        __syncthreads();
        if (tid > j && tid < 128) {
            float lij = sA[tid * 128 + j];
            for (int k = j + 1; k <= tid; k++) sA[tid * 128 + k] -= lij * sA[k * 128 + j];
        }
        __syncthreads();
    }

    float ld = (tid < 128) ? logf(sA[tid * 129]) : 0.0f;
    float logdetA = 2.0f * blk_sum(ld, red);

    for (int i = tid; i < 16384; i += 256) sLi[i] = 0.0f;
    __syncthreads();
    if (tid < 128) {
        int j = tid;
        sLi[j * 128 + j] = 1.0f / sA[j * 128 + j];
        for (int i = j + 1; i < 128; i++) {
            float s = 0.0f;
            for (int k = j; k < i; k++) s += sA[i * 128 + k] * sLi[k * 128 + j];
            sLi[i * 128 + j] = -s / sA[i * 128 + i];
        }
    }
    __syncthreads();

    float tr = 0.0f;
    for (int i = tid; i < 16384; i += 256) tr += sLi[i] * sLi[i];
    float tr_Ainv = blk_sum(tr, red);

    for (int idx = tid; idx < 8192; idx += 256) {
        int m = idx >> 6, d = idx & 63;
        float s = 0.0f;
        for (int k = 0; k <= m; k++) s += sLi[m * 128 + k] * sC[k * 64 + d];
        sS[idx] = s;
    }
    __syncthreads();

    float mu = 0.0f;
    for (int idx = tid; idx < 8192; idx += 256) {
        int m = idx >> 6, d = idx & 63;
        float s = 0.0f;
        for (int k = m; k < 128; k++) s += sLi[k * 128 + m] * sS[k * 64 + d];
        g_W[(size_t)bh * 8192 + idx] = s;
        mu += s * s;
    }
    float mu_norm2 = blk_sum(mu, red);

    for (int idx = tid; idx < 16384; idx += 256) {
        int a = idx >> 7, b = idx & 127;
        int k0 = a > b ? a : b;
        float s = 0.0f;
        for (int k = k0; k < 128; k++) s += sLi[k * 128 + a] * sLi[k * 128 + b];
        g_P[(size_t)bh * 16384 + idx] = s;
    }

    if (tid == 0) {
        float kl = 0.5f * (64.0f * sigma2 * tr_Ainv + mu_norm2 - 8192.0f
                           - 64.0f * (128.0f * logf(sigma2) - logdetA));
        g_klbh[bh] = kl;
    }
}

// ---------------- K56 ----------------
__global__ void __launch_bounds__(256) k56_mean(const float* __restrict__ log_sigma2,
                                               const float* __restrict__ eps) {
    extern __shared__ float sm[];
    float* sPW = sm;            // 128x192
    float* sph = sm + 24576;    // 128x64  (m-major: [m][l])
    int lq = blockIdx.x, bh = blockIdx.y;
    int b = bh / Hn, h = bh % Hn;
    int tid = threadIdx.x;
    int tx = tid & 15, ty = tid >> 4;
    float sigma2 = expf(log_sigma2[0]);
    const float* Pb = g_P + (size_t)bh * 16384;
    const float* Wb = g_W + (size_t)bh * 8192;

#pragma unroll
    for (int q = 0; q < 24; q++) {
        int w = (tid + 256 * q) * 4;
        int k = w / 192, c = w - k * 192;
        float4 val = (c < 128) ? *(const float4*)(Pb + k * 128 + c)
                               : *(const float4*)(Wb + k * 64 + (c - 128));
        *(float4*)(sPW + w) = val;
    }

    int pl = tid & 63, pm = (tid >> 6) * 32;
    for (int t4 = 0; t4 < 4; t4++) {
        __syncthreads();
        int l0 = lq * 256 + t4 * 64;
        const float* prow = g_phi + ((size_t)bh * Ln + l0 + pl) * MN + pm;
#pragma unroll
        for (int e = 0; e < 8; e++) {
            float4 pv = *(const float4*)(prow + e * 4);
            sph[(pm + e*4 + 0) * 64 + pl] = pv.x;
            sph[(pm + e*4 + 1) * 64 + pl] = pv.y;
            sph[(pm + e*4 + 2) * 64 + pl] = pv.z;
            sph[(pm + e*4 + 3) * 64 + pl] = pv.w;
        }
        __syncthreads();

        float acc[4][12] = {};
#pragma unroll 8
        for (int kk = 0; kk < 128; kk++) {
            float4 a = *(const float4*)&sph[kk * 64 + ty * 4];
            float av[4] = {a.x, a.y, a.z, a.w};
            const float* br = sPW + kk * 192 + tx;
#pragma unroll
            for (int c = 0; c < 12; c++) {
                float bvv = br[c * 16];
#pragma unroll
                for (int i = 0; i < 4; i++) acc[i][c] += av[i] * bvv;
            }
        }

#pragma unroll
        for (int i = 0; i < 4; i++) {
            int l = l0 + ty * 4 + i;
            float vr = 0.0f;
#pragma unroll
            for (int c = 0; c < 8; c++) vr += acc[i][c] * sph[(tx + 16*c) * 64 + ty * 4 + i];
            vr += __shfl_xor_sync(0xffffffffu, vr, 1);
            vr += __shfl_xor_sync(0xffffffffu, vr, 2);
            vr += __shfl_xor_sync(0xffffffffu, vr, 4);
            vr += __shfl_xor_sync(0xffffffffu, vr, 8);
            float stdv = sqrtf(fmaxf(sigma2 * vr, 0.0f));
            const float* erow = eps + ((size_t)bh * Ln + l) * DV;
            float* orow = g_sf + ((size_t)(b * Ln) + l) * HDIM + h * DV;
#pragma unroll
            for (int c = 0; c < 4; c++) {
                int d = tx + 16 * c;
                orow[d] = acc[i][8 + c] + stdv * erow[d];
            }
        }
    }
}

// ---------------- K8 ----------------
__global__ void k8_kl(float* __restrict__ out, int pos) {
    __shared__ float red[8];
    float s = 0.0f;
    for (int i = threadIdx.x; i < BH; i += 256) s += g_klbh[i];
    s = blk_sum(s, red);
    if (threadIdx.x == 0) out[pos] = s * (1.0f / (float)Bn);
}

// ---------------- launcher ----------------
extern "C" void kernel_launch(void* const* d_in, const int* in_sizes, int n_in,
                              void* d_out, int out_size) {
    const float* x          = (const float*)d_in[0];
    const float* W_qv       = (const float*)d_in[1];
    const float* log_sf     = (const float*)d_in[2];
    const float* log_ls     = (const float*)d_in[3];
    const float* log_sigma2 = (const float*)d_in[4];
    const float* omega_half = (const float*)d_in[5];
    const float* phase      = (const float*)d_in[6];
    const float* W_O_w      = (const float*)d_in[7];
    const float* W_O_b      = (const float*)d_in[8];
    const float* eps        = (const float*)d_in[9];
    float* out = (float*)d_out;

    cudaFuncSetAttribute(k4_factor, cudaFuncAttributeMaxDynamicSharedMemorySize, 196608);
    cudaFuncSetAttribute(k56_mean,  cudaFuncAttributeMaxDynamicSharedMemorySize, 131072);

    k0_prep<<<192, 256>>>(log_sf, log_ls, omega_half);
    gemm768<<<dim3(12, 256), 256>>>(x, W_qv, 0, (const float*)0, (float*)0);
    k2_phi<<<dim3(16, BH), 256>>>(phase);
    k3_gram<<<dim3(2, BH), 256>>>();
    k4_factor<<<BH, 256, 196608>>>(log_sigma2);
    k56_mean<<<dim3(4, BH), 256, 131072>>>(log_sigma2, eps);
    gemm768<<<dim3(6, 256), 256>>>((const float*)0, W_O_w, 1, W_O_b, out);
    k8_kl<<<1, 256>>>(out, out_size - 1);
}